// round 9
// baseline (speedup 1.0000x reference)
#include <cuda_runtime.h>
#include <math.h>

// Problem constants (fixed shapes)
#define NPG     100     // nodes per graph
#define EPG     1600    // edges per graph
#define NH      64      // hidden width
#define NINP    3
#define H2      32
#define NOUT    10
#define STRIDE  68      // feature row stride in floats (272B: 16B-aligned, bank-friendly)
#define NTHREADS 256
#define EPAD    1952    // max padded edges: 1600 + 3*100 rounded up

typedef unsigned long long ull;
struct __align__(16) ull2x { ull a, b; };

// ---- packed f32x2 helpers (FFMA2 path; ptxas never emits these from C++) ----
__device__ __forceinline__ ull packf2(float lo, float hi) {
    ull r; asm("mov.b64 %0,{%1,%2};" : "=l"(r) : "f"(lo), "f"(hi)); return r;
}
__device__ __forceinline__ void unpackf2(ull v, float& lo, float& hi) {
    asm("mov.b64 {%0,%1},%2;" : "=f"(lo), "=f"(hi) : "l"(v));
}
__device__ __forceinline__ void fma2(ull& d, ull a, ull b) {
    asm("fma.rn.f32x2 %0,%1,%2,%0;" : "+l"(d) : "l"(a), "l"(b));
}
__device__ __forceinline__ ull mul2(ull a, ull b) {
    ull r; asm("mul.rn.f32x2 %0,%1,%2;" : "=l"(r) : "l"(a), "l"(b)); return r;
}
__device__ __forceinline__ ull add2(ull a, ull b) {
    ull r; asm("add.rn.f32x2 %0,%1,%2;" : "=l"(r) : "l"(a), "l"(b)); return r;
}

// ---------------- shared memory layout (floats) ----------------
// bufA 6800 | bufB 6800 | Wbuf 4096 | edata EPAD*2 (float2/edge, rows padded to mult-of-4)
// then rowptr[104] cnt[104] dis[100] wsum[8] gv[64] hv[32] zv[16]
struct SmemLayout {
    static constexpr int bufA_off   = 0;
    static constexpr int bufB_off   = NPG * STRIDE;
    static constexpr int Wbuf_off   = bufB_off + NPG * STRIDE;     // 13600
    static constexpr int edata_off  = Wbuf_off + 64 * 64;          // 17696 (byte off %16 == 0)
    static constexpr int floats_end = edata_off + EPAD * 2;
    static constexpr int total_bytes = floats_end * 4 + (104 + 104 + 100 + 8 + 64 + 32 + 16) * 4 + 16;
};

// ---------------- Lhat (64-wide) via per-graph padded CSR gather, f32x2 ----------------
// Every row's edge span [rowptr[i], rowptr[i+1]) is a multiple of 4 (zero-coef
// dummies at off=0), so the loop is tail-free and two edges load per LDS.128.
// dst[i][:] = cheb ? 2*(cl*src[i] + sum coef*src[col]) - dst[i] : (...)
__device__ __forceinline__ void lhat64(
    float* dst, const float* src, bool cheb,
    const float2* edata, const int* rowptr, float cl, int tid)
{
    const int j  = tid & 31;          // lane: owns cols 2j, 2j+1
    const int rg = tid >> 5;          // warp: owns rows rg, rg+8, ...
    const ull cl2 = packf2(cl, cl);
    const char* sbase = (const char*)src + j * 8;
    for (int i = rg; i < NPG; i += 8) {
        ull a0 = mul2(cl2, *(const ull*)(src + i * STRIDE + 2 * j));
        ull a1 = packf2(0.f, 0.f);
        const int eEnd = rowptr[i + 1];
        for (int e = rowptr[i]; e < eEnd; e += 4) {
            float4 p0 = *(const float4*)(edata + e);       // (c0, off0, c1, off1): LDS.128 bcast
            float4 p1 = *(const float4*)(edata + e + 2);
            ull s0 = *(const ull*)(sbase + __float_as_int(p0.y));  // LDS.64 gather, conflict-free
            ull s1 = *(const ull*)(sbase + __float_as_int(p0.w));
            ull s2 = *(const ull*)(sbase + __float_as_int(p1.y));
            ull s3 = *(const ull*)(sbase + __float_as_int(p1.w));
            fma2(a0, packf2(p0.x, p0.x), s0);
            fma2(a1, packf2(p0.z, p0.z), s1);
            fma2(a0, packf2(p1.x, p1.x), s2);
            fma2(a1, packf2(p1.z, p1.z), s3);
        }
        ull a = add2(a0, a1);
        float lo, hi; unpackf2(a, lo, hi);
        float* drow = dst + i * STRIDE + 2 * j;
        if (cheb) {
            float2 d = *(float2*)drow;
            *(float2*)drow = make_float2(2.0f * lo - d.x, 2.0f * hi - d.y);
        } else {
            *(float2*)drow = make_float2(lo, hi);
        }
    }
    __syncthreads();
}

__device__ __forceinline__ void lhat3(
    float* dst, const float* src, bool cheb,
    const float2* edata, const int* rowptr, float cl, int tid)
{
    if (tid < NPG) {
        const int i = tid;
        const float* srow = src + i * STRIDE;
        float a0 = cl * srow[0], a1 = cl * srow[1], a2 = cl * srow[2];
        const int e1 = rowptr[i + 1];
        for (int e = rowptr[i]; e < e1; e++) {    // dummies: coef 0, harmless
            float2 ed = edata[e];
            const float* sc = (const float*)((const char*)src + __float_as_int(ed.y));
            a0 = fmaf(ed.x, sc[0], a0);
            a1 = fmaf(ed.x, sc[1], a1);
            a2 = fmaf(ed.x, sc[2], a2);
        }
        float* drow = dst + i * STRIDE;
        if (cheb) {
            drow[0] = 2.0f * a0 - drow[0];
            drow[1] = 2.0f * a1 - drow[1];
            drow[2] = 2.0f * a2 - drow[2];
        } else {
            drow[0] = a0; drow[1] = a1; drow[2] = a2;
        }
    }
    __syncthreads();
}

// ---------------- GEMM: acc[112x64] += Tx[.xCIN] @ W[CINx64] ----------------
// tx = tid&15 owns cols [4tx,4tx+4) (2 f32x2 pairs); ty = tid>>4 owns rows
// ty+16r, r=0..6 (row 96+ty valid only for ty<4). Rows 100..111 compute garbage
// inside smem bounds and are never stored. W chunk (4 k-rows) kept resident,
// tv loaded per row (broadcast LDS.128) -> lower peak register pressure.
// No trailing syncthreads: row sharing is intra-warp; Wbuf hazards covered by
// the surrounding lhat/layer barriers.
template<int CIN>
__device__ __forceinline__ void gemm_acc(
    ull (&acc)[7][2], const float* __restrict__ Tx,
    const float* __restrict__ Wg, float* Wbuf, int tid)
{
    for (int idx = tid; idx < CIN * 16; idx += NTHREADS)
        ((float4*)Wbuf)[idx] = ((const float4*)Wg)[idx];
    __syncthreads();
    const int tx = tid & 15, ty = tid >> 4;
    if (CIN == 3) {
        #pragma unroll
        for (int k = 0; k < 3; k++) {
            ull2x w = *(const ull2x*)(Wbuf + k * 64 + tx * 4);      // LDS.128
            #pragma unroll
            for (int r = 0; r < 7; r++) {
                float t = Tx[(ty + 16 * r) * STRIDE + k];
                ull t2 = packf2(t, t);
                fma2(acc[r][0], t2, w.a);
                fma2(acc[r][1], t2, w.b);
            }
        }
    } else {
        #pragma unroll 2
        for (int kc = 0; kc < CIN / 4; kc++) {
            ull w[4][2];
            #pragma unroll
            for (int q = 0; q < 4; q++) {
                ull2x ww = *(const ull2x*)(Wbuf + (kc * 4 + q) * 64 + tx * 4);  // LDS.128
                w[q][0] = ww.a; w[q][1] = ww.b;
            }
            #pragma unroll
            for (int r = 0; r < 7; r++) {
                float4 tv = *(const float4*)(Tx + (ty + 16 * r) * STRIDE + kc * 4); // LDS.128 bcast
                ull t0 = packf2(tv.x, tv.x);
                fma2(acc[r][0], t0, w[0][0]); fma2(acc[r][1], t0, w[0][1]);
                ull t1 = packf2(tv.y, tv.y);
                fma2(acc[r][0], t1, w[1][0]); fma2(acc[r][1], t1, w[1][1]);
                ull t2 = packf2(tv.z, tv.z);
                fma2(acc[r][0], t2, w[2][0]); fma2(acc[r][1], t2, w[2][1]);
                ull t3 = packf2(tv.w, tv.w);
                fma2(acc[r][0], t3, w[3][0]); fma2(acc[r][1], t3, w[3][1]);
            }
        }
    }
}

// ---------------- One ChebConv layer (+bias +ReLU) -> bufA ----------------
template<int CIN>
__device__ __noinline__ void cheb_layer(
    float* bufA, float* bufB, float* Wbuf,
    const float* __restrict__ Wg, const float* __restrict__ bg,
    const float2* edata, const int* rowptr, float cl, int tid)
{
    ull acc[7][2];
    #pragma unroll
    for (int r = 0; r < 7; r++) { acc[r][0] = 0ull; acc[r][1] = 0ull; }

    gemm_acc<CIN>(acc, bufA, Wg, Wbuf, tid);                 // k=0: Tx0 = X
    if (CIN == 3) lhat3(bufB, bufA, false, edata, rowptr, cl, tid);
    else          lhat64(bufB, bufA, false, edata, rowptr, cl, tid);
    gemm_acc<CIN>(acc, bufB, Wg + 1 * CIN * 64, Wbuf, tid);  // k=1
    if (CIN == 3) lhat3(bufA, bufB, true, edata, rowptr, cl, tid);
    else          lhat64(bufA, bufB, true, edata, rowptr, cl, tid);
    gemm_acc<CIN>(acc, bufA, Wg + 2 * CIN * 64, Wbuf, tid);  // k=2
    if (CIN == 3) lhat3(bufB, bufA, true, edata, rowptr, cl, tid);
    else          lhat64(bufB, bufA, true, edata, rowptr, cl, tid);
    gemm_acc<CIN>(acc, bufB, Wg + 3 * CIN * 64, Wbuf, tid);  // k=3
    if (CIN == 3) lhat3(bufA, bufB, true, edata, rowptr, cl, tid);
    else          lhat64(bufA, bufB, true, edata, rowptr, cl, tid);
    gemm_acc<CIN>(acc, bufA, Wg + 4 * CIN * 64, Wbuf, tid);  // k=4

    // h = relu(acc + b) -> bufA (rows owned intra-warp; safe vs k=4 reads)
    const int tx = tid & 15, ty = tid >> 4;
    float4 bb = *(const float4*)(bg + tx * 4);
    #pragma unroll
    for (int r = 0; r < 7; r++) {
        if (r < 6 || ty < 4) {
            float v0, v1, v2, v3;
            unpackf2(acc[r][0], v0, v1);
            unpackf2(acc[r][1], v2, v3);
            float4 o = make_float4(fmaxf(v0 + bb.x, 0.f), fmaxf(v1 + bb.y, 0.f),
                                   fmaxf(v2 + bb.z, 0.f), fmaxf(v3 + bb.w, 0.f));
            *(float4*)(bufA + (ty + 16 * r) * STRIDE + tx * 4) = o;
        }
    }
    __syncthreads();
}

// ---------------- main kernel: one CTA per graph ----------------
__global__ __launch_bounds__(NTHREADS, 2)
void chebnet_kernel(
    const float* __restrict__ x, const int* __restrict__ ei,
    const float* __restrict__ lambda_max,
    const float* __restrict__ W1, const float* __restrict__ b1,
    const float* __restrict__ W2, const float* __restrict__ b2,
    const float* __restrict__ W3, const float* __restrict__ b3,
    const float* __restrict__ bn_g, const float* __restrict__ bn_b,
    const float* __restrict__ bn_m, const float* __restrict__ bn_v,
    const float* __restrict__ fc1w, const float* __restrict__ fc1b,
    const float* __restrict__ fc2w, const float* __restrict__ fc2b,
    float* __restrict__ out, int E)
{
    extern __shared__ float smem_f[];
    float*  bufA   = smem_f + SmemLayout::bufA_off;
    float*  bufB   = smem_f + SmemLayout::bufB_off;
    float*  Wbuf   = smem_f + SmemLayout::Wbuf_off;
    float2* edata  = (float2*)(smem_f + SmemLayout::edata_off);
    int*    rowptr = (int*)(smem_f + SmemLayout::floats_end);
    int*    cnt    = rowptr + 104;
    float*  dis    = (float*)(cnt + 104);
    int*    wsum   = (int*)(dis + 100);
    float*  gv     = (float*)(wsum + 8);
    float*  hv     = gv + 64;
    float*  zv     = hv + 32;

    const int g = blockIdx.x, tid = threadIdx.x;
    const int nbase = g * NPG, ebase = g * EPG;

    if (tid < NPG) cnt[tid] = 0;
    __syncthreads();

    // Pass 1: stage packed (src,dst) local edges in bufB, histogram per src row.
    int* stage = (int*)bufB;
    for (int e = tid; e < EPG; e += NTHREADS) {
        int s = ei[ebase + e] - nbase;
        int d = ei[E + ebase + e] - nbase;
        stage[e] = (s << 8) | d;
        atomicAdd(&cnt[s], 1);
    }
    // Load node features X into bufA (cols 0..2).
    for (int idx = tid; idx < NPG * NINP; idx += NTHREADS) {
        int i = idx / NINP, c = idx - i * NINP;
        bufA[i * STRIDE + c] = x[(nbase + i) * NINP + c];
    }
    __syncthreads();

    // Parallel exclusive scan of per-row capacities (deg padded to mult-of-4).
    const int deg = (tid < NPG) ? cnt[tid] : 0;
    if (tid < NPG) dis[tid] = (deg > 0) ? rsqrtf((float)deg) : 0.0f;
    {
        int cap = (deg + 3) & ~3;
        int v = cap;
        #pragma unroll
        for (int dlt = 1; dlt < 32; dlt <<= 1) {
            int n = __shfl_up_sync(0xFFFFFFFFu, v, dlt);
            if ((tid & 31) >= dlt) v += n;
        }
        if ((tid & 31) == 31) wsum[tid >> 5] = v;
        __syncthreads();
        int woff = 0;
        #pragma unroll
        for (int w = 0; w < 8; w++) woff += (w < (tid >> 5)) ? wsum[w] : 0;
        int incl = v + woff;
        if (tid < NPG)     rowptr[tid] = incl - cap;   // exclusive (mult of 4)
        if (tid == NPG - 1) rowptr[NPG] = incl;
    }
    __syncthreads();
    if (tid < NPG) cnt[tid] = rowptr[tid];             // cursor
    const float lmx = lambda_max[g];
    const float s2  = 2.0f / lmx;
    const float cl  = s2 - 1.0f;
    __syncthreads();

    // Pass 2: CSR fill -> edata[e] = (coef, dst_byte_offset).
    for (int e = tid; e < EPG; e += NTHREADS) {
        int pk = stage[e];
        int s = pk >> 8, d = pk & 255;
        int pos = atomicAdd(&cnt[s], 1);
        float c = -s2 * dis[s] * dis[d];
        edata[pos] = make_float2(c, __int_as_float(d * (STRIDE * 4)));
    }
    __syncthreads();

    // Tail pad each row to its mult-of-4 capacity with zero-coef dummies.
    if (tid < NPG) {
        const float2 dummy = make_float2(0.f, __int_as_float(0));
        for (int p = cnt[tid]; p < rowptr[tid + 1]; p++) edata[p] = dummy;
    }
    __syncthreads();

    // 3 ChebConv layers
    cheb_layer<NINP>(bufA, bufB, Wbuf, W1, b1, edata, rowptr, cl, tid);
    cheb_layer<NH>  (bufA, bufB, Wbuf, W2, b2, edata, rowptr, cl, tid);
    cheb_layer<NH>  (bufA, bufB, Wbuf, W3, b3, edata, rowptr, cl, tid);

    // mean pool + BatchNorm (eval)
    if (tid < NH) {
        float s = 0.0f;
        for (int i = 0; i < NPG; i++) s += bufA[i * STRIDE + tid];
        float gm = s * (1.0f / (float)NPG);
        gv[tid] = (gm - bn_m[tid]) * rsqrtf(bn_v[tid] + 1e-5f) * bn_g[tid] + bn_b[tid];
    }
    __syncthreads();
    if (tid < H2) {
        float a = fc1b[tid];
        for (int j = 0; j < NH; j++) a = fmaf(gv[j], fc1w[j * H2 + tid], a);
        hv[tid] = fmaxf(a, 0.0f);
    }
    __syncthreads();
    if (tid < NOUT) {
        float a = fc2b[tid];
        for (int m = 0; m < H2; m++) a = fmaf(hv[m], fc2w[m * NOUT + tid], a);
        zv[tid] = a;
    }
    __syncthreads();
    if (tid == 0) {
        float mx = zv[0];
        #pragma unroll
        for (int c = 1; c < NOUT; c++) mx = fmaxf(mx, zv[c]);
        float se = 0.0f;
        #pragma unroll
        for (int c = 0; c < NOUT; c++) se += expf(zv[c] - mx);
        float lse = mx + logf(se);
        #pragma unroll
        for (int c = 0; c < NOUT; c++) out[g * NOUT + c] = zv[c] - lse;
    }
}

extern "C" void kernel_launch(void* const* d_in, const int* in_sizes, int n_in,
                              void* d_out, int out_size)
{
    const float* x    = (const float*)d_in[0];
    const int*   ei   = (const int*)  d_in[1];
    const float* lmax = (const float*)d_in[3];
    const float* W1   = (const float*)d_in[4];
    const float* b1   = (const float*)d_in[5];
    const float* W2   = (const float*)d_in[6];
    const float* b2   = (const float*)d_in[7];
    const float* W3   = (const float*)d_in[8];
    const float* b3   = (const float*)d_in[9];
    const float* bn_g = (const float*)d_in[10];
    const float* bn_b = (const float*)d_in[11];
    const float* bn_m = (const float*)d_in[12];
    const float* bn_v = (const float*)d_in[13];
    const float* fc1w = (const float*)d_in[14];
    const float* fc1b = (const float*)d_in[15];
    const float* fc2w = (const float*)d_in[16];
    const float* fc2b = (const float*)d_in[17];
    float* out = (float*)d_out;

    const int E = in_sizes[1] / 2;
    const int G = in_sizes[3];

    const int smem_bytes = SmemLayout::total_bytes;
    cudaFuncSetAttribute(chebnet_kernel,
                         cudaFuncAttributeMaxDynamicSharedMemorySize, smem_bytes);

    chebnet_kernel<<<G, NTHREADS, smem_bytes>>>(
        x, ei, lmax, W1, b1, W2, b2, W3, b3,
        bn_g, bn_b, bn_m, bn_v, fc1w, fc1b, fc2w, fc2b, out, E);
}

// round 10
// speedup vs baseline: 1.0325x; 1.0325x over previous
#include <cuda_runtime.h>
#include <math.h>

// Problem constants (fixed shapes)
#define NPG     100     // nodes per graph
#define EPG     1600    // edges per graph
#define NH      64      // hidden width
#define NINP    3
#define H2      32
#define NOUT    10
#define STRIDE  68      // feature row stride in floats (272B: 16B-aligned, bank-friendly)
#define NTHREADS 256

typedef unsigned long long ull;

// ---- packed f32x2 helpers (FFMA2 path; ptxas never emits these from C++) ----
__device__ __forceinline__ ull packf2(float lo, float hi) {
    ull r; asm("mov.b64 %0,{%1,%2};" : "=l"(r) : "f"(lo), "f"(hi)); return r;
}
__device__ __forceinline__ void unpackf2(ull v, float& lo, float& hi) {
    asm("mov.b64 {%0,%1},%2;" : "=f"(lo), "=f"(hi) : "l"(v));
}
__device__ __forceinline__ void fma2(ull& d, ull a, ull b) {
    asm("fma.rn.f32x2 %0,%1,%2,%0;" : "+l"(d) : "l"(a), "l"(b));
}
__device__ __forceinline__ ull mul2(ull a, ull b) {
    ull r; asm("mul.rn.f32x2 %0,%1,%2;" : "=l"(r) : "l"(a), "l"(b)); return r;
}
__device__ __forceinline__ ull add2(ull a, ull b) {
    ull r; asm("add.rn.f32x2 %0,%1,%2;" : "=l"(r) : "l"(a), "l"(b)); return r;
}

// ---------------- shared memory layout (floats) ----------------
// bufA 6800 | bufB 6800 | edata EPG*2 (float2/edge)
// then rowptr[104] cnt[104] dis[100] wsum[8] gv[64] hv[32] zv[16]
// NO Wbuf: gemm streams W from global (L2-resident, shared by all CTAs).
struct SmemLayout {
    static constexpr int bufA_off   = 0;
    static constexpr int bufB_off   = NPG * STRIDE;
    static constexpr int edata_off  = bufB_off + NPG * STRIDE;     // 13600 (byte off %16==0)
    static constexpr int floats_end = edata_off + EPG * 2;         // 16800
    static constexpr int total_bytes = floats_end * 4 + (104 + 104 + 100 + 8 + 64 + 32 + 16) * 4 + 16;
};

// ---------------- Lhat (64-wide) via per-graph CSR gather, f32x2 (R6 form) --------
// dst[i][:] = cheb ? 2*(cl*src[i] + sum coef*src[col]) - dst[i] : (...)
__device__ __forceinline__ void lhat64(
    float* dst, const float* src, bool cheb,
    const float2* edata, const int* rowptr, float cl, int tid)
{
    const int j  = tid & 31;          // lane: owns cols 2j, 2j+1
    const int rg = tid >> 5;          // warp: owns rows rg, rg+8, ...
    const ull cl2 = packf2(cl, cl);
    const char* sbase = (const char*)src + j * 8;
    for (int i = rg; i < NPG; i += 8) {
        ull a0 = mul2(cl2, *(const ull*)(src + i * STRIDE + 2 * j));
        ull a1 = packf2(0.f, 0.f);
        const int eBeg = rowptr[i], eEnd = rowptr[i + 1];
        int e = eBeg;
        for (; e + 1 < eEnd; e += 2) {
            float2 ed0 = edata[e];                                  // LDS.64 broadcast
            float2 ed1 = edata[e + 1];
            ull s0 = *(const ull*)(sbase + __float_as_int(ed0.y));  // LDS.64 gather, conflict-free
            ull s1 = *(const ull*)(sbase + __float_as_int(ed1.y));
            fma2(a0, packf2(ed0.x, ed0.x), s0);
            fma2(a1, packf2(ed1.x, ed1.x), s1);
        }
        if (e < eEnd) {
            float2 ed0 = edata[e];
            ull s0 = *(const ull*)(sbase + __float_as_int(ed0.y));
            fma2(a0, packf2(ed0.x, ed0.x), s0);
        }
        ull a = add2(a0, a1);
        float lo, hi; unpackf2(a, lo, hi);
        float* drow = dst + i * STRIDE + 2 * j;
        if (cheb) {
            float2 d = *(float2*)drow;
            *(float2*)drow = make_float2(2.0f * lo - d.x, 2.0f * hi - d.y);
        } else {
            *(float2*)drow = make_float2(lo, hi);
        }
    }
    __syncthreads();
}

__device__ __forceinline__ void lhat3(
    float* dst, const float* src, bool cheb,
    const float2* edata, const int* rowptr, float cl, int tid)
{
    if (tid < NPG) {
        const int i = tid;
        const float* srow = src + i * STRIDE;
        float a0 = cl * srow[0], a1 = cl * srow[1], a2 = cl * srow[2];
        const int e1 = rowptr[i + 1];
        for (int e = rowptr[i]; e < e1; e++) {
            float2 ed = edata[e];
            const float* sc = (const float*)((const char*)src + __float_as_int(ed.y));
            a0 = fmaf(ed.x, sc[0], a0);
            a1 = fmaf(ed.x, sc[1], a1);
            a2 = fmaf(ed.x, sc[2], a2);
        }
        float* drow = dst + i * STRIDE;
        if (cheb) {
            drow[0] = 2.0f * a0 - drow[0];
            drow[1] = 2.0f * a1 - drow[1];
            drow[2] = 2.0f * a2 - drow[2];
        } else {
            drow[0] = a0; drow[1] = a1; drow[2] = a2;
        }
    }
    __syncthreads();
}

// ---------------- GEMM: acc[112x64] += Tx[.xCIN] @ W[CINx64] ----------------
// tx = tid&15 owns cols [4tx,4tx+4) (2 f32x2 pairs); ty = tid>>4 owns rows
// ty+16r, r=0..6 (row 96+ty valid only for ty<4). Rows 100..111 compute garbage
// inside smem bounds and are never stored.
// W is read straight from global via LDG.128 (__ldg): L2-resident, shared by
// all CTAs; no smem staging, NO BARRIERS inside gemm. Tx read from smem
// (broadcast LDS.128 per row).
template<int CIN>
__device__ __forceinline__ void gemm_acc(
    ull (&acc)[7][2], const float* __restrict__ Tx,
    const float* __restrict__ Wg, int tid)
{
    const int tx = tid & 15, ty = tid >> 4;
    const float4* W4 = (const float4*)Wg;         // 16 float4 per k-row
    if (CIN == 3) {
        #pragma unroll
        for (int k = 0; k < 3; k++) {
            float4 wv = __ldg(W4 + k * 16 + tx);
            ull wa = packf2(wv.x, wv.y), wb = packf2(wv.z, wv.w);
            #pragma unroll
            for (int r = 0; r < 7; r++) {
                float t = Tx[(ty + 16 * r) * STRIDE + k];
                ull t2 = packf2(t, t);
                fma2(acc[r][0], t2, wa);
                fma2(acc[r][1], t2, wb);
            }
        }
    } else {
        #pragma unroll 2
        for (int kc = 0; kc < CIN / 4; kc++) {
            float4 wv[4];
            #pragma unroll
            for (int q = 0; q < 4; q++)
                wv[q] = __ldg(W4 + (kc * 4 + q) * 16 + tx);   // LDG.128 (L2 hit)
            ull w[4][2];
            #pragma unroll
            for (int q = 0; q < 4; q++) {
                w[q][0] = packf2(wv[q].x, wv[q].y);
                w[q][1] = packf2(wv[q].z, wv[q].w);
            }
            #pragma unroll
            for (int r = 0; r < 7; r++) {
                float4 tv = *(const float4*)(Tx + (ty + 16 * r) * STRIDE + kc * 4); // LDS.128 bcast
                ull t0 = packf2(tv.x, tv.x);
                fma2(acc[r][0], t0, w[0][0]); fma2(acc[r][1], t0, w[0][1]);
                ull t1 = packf2(tv.y, tv.y);
                fma2(acc[r][0], t1, w[1][0]); fma2(acc[r][1], t1, w[1][1]);
                ull t2 = packf2(tv.z, tv.z);
                fma2(acc[r][0], t2, w[2][0]); fma2(acc[r][1], t2, w[2][1]);
                ull t3 = packf2(tv.w, tv.w);
                fma2(acc[r][0], t3, w[3][0]); fma2(acc[r][1], t3, w[3][1]);
            }
        }
    }
}

// ---------------- One ChebConv layer (+bias +ReLU) -> bufA ----------------
// Hazard chain without gemm barriers: every writer of bufA/bufB is separated
// from its cross-thread readers by at least one lhat trailing __syncthreads
// (or the layer-end barrier). gemm touches no shared scratch.
template<int CIN>
__device__ __noinline__ void cheb_layer(
    float* bufA, float* bufB,
    const float* __restrict__ Wg, const float* __restrict__ bg,
    const float2* edata, const int* rowptr, float cl, int tid)
{
    ull acc[7][2];
    #pragma unroll
    for (int r = 0; r < 7; r++) { acc[r][0] = 0ull; acc[r][1] = 0ull; }

    gemm_acc<CIN>(acc, bufA, Wg, tid);                 // k=0: Tx0 = X
    if (CIN == 3) lhat3(bufB, bufA, false, edata, rowptr, cl, tid);
    else          lhat64(bufB, bufA, false, edata, rowptr, cl, tid);
    gemm_acc<CIN>(acc, bufB, Wg + 1 * CIN * 64, tid);  // k=1
    if (CIN == 3) lhat3(bufA, bufB, true, edata, rowptr, cl, tid);
    else          lhat64(bufA, bufB, true, edata, rowptr, cl, tid);
    gemm_acc<CIN>(acc, bufA, Wg + 2 * CIN * 64, tid);  // k=2
    if (CIN == 3) lhat3(bufB, bufA, true, edata, rowptr, cl, tid);
    else          lhat64(bufB, bufA, true, edata, rowptr, cl, tid);
    gemm_acc<CIN>(acc, bufB, Wg + 3 * CIN * 64, tid);  // k=3
    if (CIN == 3) lhat3(bufA, bufB, true, edata, rowptr, cl, tid);
    else          lhat64(bufA, bufB, true, edata, rowptr, cl, tid);
    gemm_acc<CIN>(acc, bufA, Wg + 4 * CIN * 64, tid);  // k=4

    // h = relu(acc + b) -> bufA (rows owned intra-warp; safe vs k=4 reads)
    const int tx = tid & 15, ty = tid >> 4;
    float4 bb = __ldg((const float4*)(bg + tx * 4));
    #pragma unroll
    for (int r = 0; r < 7; r++) {
        if (r < 6 || ty < 4) {
            float v0, v1, v2, v3;
            unpackf2(acc[r][0], v0, v1);
            unpackf2(acc[r][1], v2, v3);
            float4 o = make_float4(fmaxf(v0 + bb.x, 0.f), fmaxf(v1 + bb.y, 0.f),
                                   fmaxf(v2 + bb.z, 0.f), fmaxf(v3 + bb.w, 0.f));
            *(float4*)(bufA + (ty + 16 * r) * STRIDE + tx * 4) = o;
        }
    }
    __syncthreads();
}

// ---------------- main kernel: one CTA per graph, 3 CTAs/SM ----------------
__global__ __launch_bounds__(NTHREADS, 3)
void chebnet_kernel(
    const float* __restrict__ x, const int* __restrict__ ei,
    const float* __restrict__ lambda_max,
    const float* __restrict__ W1, const float* __restrict__ b1,
    const float* __restrict__ W2, const float* __restrict__ b2,
    const float* __restrict__ W3, const float* __restrict__ b3,
    const float* __restrict__ bn_g, const float* __restrict__ bn_b,
    const float* __restrict__ bn_m, const float* __restrict__ bn_v,
    const float* __restrict__ fc1w, const float* __restrict__ fc1b,
    const float* __restrict__ fc2w, const float* __restrict__ fc2b,
    float* __restrict__ out, int E)
{
    extern __shared__ float smem_f[];
    float*  bufA   = smem_f + SmemLayout::bufA_off;
    float*  bufB   = smem_f + SmemLayout::bufB_off;
    float2* edata  = (float2*)(smem_f + SmemLayout::edata_off);
    int*    rowptr = (int*)(smem_f + SmemLayout::floats_end);
    int*    cnt    = rowptr + 104;
    float*  dis    = (float*)(cnt + 104);
    int*    wsum   = (int*)(dis + 100);
    float*  gv     = (float*)(wsum + 8);
    float*  hv     = gv + 64;
    float*  zv     = hv + 32;

    const int g = blockIdx.x, tid = threadIdx.x;
    const int nbase = g * NPG, ebase = g * EPG;

    if (tid < NPG) cnt[tid] = 0;
    __syncthreads();

    // Pass 1: stage packed (src,dst) local edges in bufB, histogram per src row.
    int* stage = (int*)bufB;
    for (int e = tid; e < EPG; e += NTHREADS) {
        int s = ei[ebase + e] - nbase;
        int d = ei[E + ebase + e] - nbase;
        stage[e] = (s << 8) | d;
        atomicAdd(&cnt[s], 1);
    }
    // Load node features X into bufA (cols 0..2).
    for (int idx = tid; idx < NPG * NINP; idx += NTHREADS) {
        int i = idx / NINP, c = idx - i * NINP;
        bufA[i * STRIDE + c] = x[(nbase + i) * NINP + c];
    }
    __syncthreads();

    // Parallel exclusive scan of per-row degrees -> rowptr.
    const int deg = (tid < NPG) ? cnt[tid] : 0;
    if (tid < NPG) dis[tid] = (deg > 0) ? rsqrtf((float)deg) : 0.0f;
    {
        int v = deg;
        #pragma unroll
        for (int dlt = 1; dlt < 32; dlt <<= 1) {
            int n = __shfl_up_sync(0xFFFFFFFFu, v, dlt);
            if ((tid & 31) >= dlt) v += n;
        }
        if ((tid & 31) == 31) wsum[tid >> 5] = v;
        __syncthreads();
        int woff = 0;
        #pragma unroll
        for (int w = 0; w < 8; w++) woff += (w < (tid >> 5)) ? wsum[w] : 0;
        int incl = v + woff;
        if (tid < NPG)      rowptr[tid] = incl - deg;   // exclusive
        if (tid == NPG - 1) rowptr[NPG] = incl;
    }
    __syncthreads();
    if (tid < NPG) cnt[tid] = rowptr[tid];              // cursor
    const float lmx = lambda_max[g];
    const float s2  = 2.0f / lmx;
    const float cl  = s2 - 1.0f;
    __syncthreads();

    // Pass 2: CSR fill -> edata[e] = (coef, dst_byte_offset).
    for (int e = tid; e < EPG; e += NTHREADS) {
        int pk = stage[e];
        int s = pk >> 8, d = pk & 255;
        int pos = atomicAdd(&cnt[s], 1);
        float c = -s2 * dis[s] * dis[d];
        edata[pos] = make_float2(c, __int_as_float(d * (STRIDE * 4)));
    }
    __syncthreads();

    // 3 ChebConv layers
    cheb_layer<NINP>(bufA, bufB, W1, b1, edata, rowptr, cl, tid);
    cheb_layer<NH>  (bufA, bufB, W2, b2, edata, rowptr, cl, tid);
    cheb_layer<NH>  (bufA, bufB, W3, b3, edata, rowptr, cl, tid);

    // mean pool + BatchNorm (eval)
    if (tid < NH) {
        float s = 0.0f;
        for (int i = 0; i < NPG; i++) s += bufA[i * STRIDE + tid];
        float gm = s * (1.0f / (float)NPG);
        gv[tid] = (gm - bn_m[tid]) * rsqrtf(bn_v[tid] + 1e-5f) * bn_g[tid] + bn_b[tid];
    }
    __syncthreads();
    if (tid < H2) {
        float a = fc1b[tid];
        for (int j = 0; j < NH; j++) a = fmaf(gv[j], fc1w[j * H2 + tid], a);
        hv[tid] = fmaxf(a, 0.0f);
    }
    __syncthreads();
    if (tid < NOUT) {
        float a = fc2b[tid];
        for (int m = 0; m < H2; m++) a = fmaf(hv[m], fc2w[m * NOUT + tid], a);
        zv[tid] = a;
    }
    __syncthreads();
    if (tid == 0) {
        float mx = zv[0];
        #pragma unroll
        for (int c = 1; c < NOUT; c++) mx = fmaxf(mx, zv[c]);
        float se = 0.0f;
        #pragma unroll
        for (int c = 0; c < NOUT; c++) se += expf(zv[c] - mx);
        float lse = mx + logf(se);
        #pragma unroll
        for (int c = 0; c < NOUT; c++) out[g * NOUT + c] = zv[c] - lse;
    }
}

extern "C" void kernel_launch(void* const* d_in, const int* in_sizes, int n_in,
                              void* d_out, int out_size)
{
    const float* x    = (const float*)d_in[0];
    const int*   ei   = (const int*)  d_in[1];
    const float* lmax = (const float*)d_in[3];
    const float* W1   = (const float*)d_in[4];
    const float* b1   = (const float*)d_in[5];
    const float* W2   = (const float*)d_in[6];
    const float* b2   = (const float*)d_in[7];
    const float* W3   = (const float*)d_in[8];
    const float* b3   = (const float*)d_in[9];
    const float* bn_g = (const float*)d_in[10];
    const float* bn_b = (const float*)d_in[11];
    const float* bn_m = (const float*)d_in[12];
    const float* bn_v = (const float*)d_in[13];
    const float* fc1w = (const float*)d_in[14];
    const float* fc1b = (const float*)d_in[15];
    const float* fc2w = (const float*)d_in[16];
    const float* fc2b = (const float*)d_in[17];
    float* out = (float*)d_out;

    const int E = in_sizes[1] / 2;
    const int G = in_sizes[3];

    const int smem_bytes = SmemLayout::total_bytes;
    cudaFuncSetAttribute(chebnet_kernel,
                         cudaFuncAttributeMaxDynamicSharedMemorySize, smem_bytes);

    chebnet_kernel<<<G, NTHREADS, smem_bytes>>>(
        x, ei, lmax, W1, b1, W2, b2, W3, b3,
        bn_g, bn_b, bn_m, bn_v, fc1w, fc1b, fc2w, fc2b, out, E);
}